// round 1
// baseline (speedup 1.0000x reference)
#include <cuda_runtime.h>
#include <cuda_bf16.h>

#define N_OPT 16
#define OUT_F 1024
#define IN_F  1024
#define BATCH 8
#define A_DIM 512

// ---- scratch (device globals: no alloc in kernel_launch) ----
__device__ float g_wmix[BATCH * OUT_F * IN_F];   // 32 MB: per-batch mixed weights [b][i][j]
__device__ float g_bmix[BATCH * OUT_F];          // per-batch mixed bias

// ============================================================
// Kernel 1: w_mixed[b][i][j] = sum_n sp[b][n] * W[n][i][j]
// Each thread owns one float4 position of the [OUT_F*IN_F] plane,
// reads the 16 expert values ONCE, accumulates all 8 batches.
// Traffic: 64 MB read + 32 MB write.
// ============================================================
__global__ void mix_weights_kernel(const float* __restrict__ W,
                                   const float* __restrict__ sp) {
    __shared__ float s_sp[BATCH * N_OPT];
    if (threadIdx.x < BATCH * N_OPT) s_sp[threadIdx.x] = sp[threadIdx.x];
    __syncthreads();

    const int t = blockIdx.x * blockDim.x + threadIdx.x;    // float4 index in plane
    const int plane4 = (OUT_F * IN_F) / 4;                  // 262144
    if (t >= plane4) return;

    const float4* W4 = reinterpret_cast<const float4*>(W);

    float4 acc[BATCH];
#pragma unroll
    for (int b = 0; b < BATCH; b++) acc[b] = make_float4(0.f, 0.f, 0.f, 0.f);

#pragma unroll
    for (int n = 0; n < N_OPT; n++) {
        float4 w = W4[(size_t)n * plane4 + t];
#pragma unroll
        for (int b = 0; b < BATCH; b++) {
            float s = s_sp[b * N_OPT + n];
            acc[b].x += s * w.x;
            acc[b].y += s * w.y;
            acc[b].z += s * w.z;
            acc[b].w += s * w.w;
        }
    }

    float4* out4 = reinterpret_cast<float4*>(g_wmix);
#pragma unroll
    for (int b = 0; b < BATCH; b++) out4[(size_t)b * plane4 + t] = acc[b];
}

// ============================================================
// Kernel 2: b_mixed[b][i] = sum_n sp[b][n] * bias[n][i]
// ============================================================
__global__ void mix_bias_kernel(const float* __restrict__ bias,
                                const float* __restrict__ sp) {
    int tid = blockIdx.x * blockDim.x + threadIdx.x;   // [0, BATCH*OUT_F)
    if (tid >= BATCH * OUT_F) return;
    int b = tid / OUT_F;
    int i = tid % OUT_F;
    float acc = 0.f;
#pragma unroll
    for (int n = 0; n < N_OPT; n++) acc += sp[b * N_OPT + n] * bias[n * OUT_F + i];
    g_bmix[tid] = acc;
}

// ============================================================
// Kernel 3: batched SGEMM (NT): out[b][a][i] = sum_j x[b][a][j]*w_mixed[b][i][j] + b_mixed[b][i]
// Tiles: BM=128 (a), BN=128 (i), BK=16 (j). 256 threads, 8x8 per thread.
// ============================================================
#define BM 128
#define BN 128
#define BK 16

__global__ void __launch_bounds__(256, 2)
gemm_kernel(const float* __restrict__ x, float* __restrict__ out) {
    const int b  = blockIdx.z;
    const float* Ag = x + (size_t)b * A_DIM * IN_F;                 // [512,1024]
    const float* Bg = g_wmix + (size_t)b * OUT_F * IN_F;            // [1024,1024]

    __shared__ float As[BK][BM + 1];
    __shared__ float Bs[BK][BN + 1];

    const int tid = threadIdx.x;
    const int tx = tid & 15;       // 0..15 -> N direction
    const int ty = tid >> 4;       // 0..15 -> M direction

    const int rowA0 = blockIdx.y * BM;    // a offset
    const int rowB0 = blockIdx.x * BN;    // i offset

    float acc[8][8];
#pragma unroll
    for (int m = 0; m < 8; m++)
#pragma unroll
        for (int n = 0; n < 8; n++) acc[m][n] = 0.f;

    for (int k0 = 0; k0 < IN_F; k0 += BK) {
        // load tiles: 128 rows x 16 cols = 512 float4 each; 256 threads x 2
#pragma unroll
        for (int i = 0; i < 2; i++) {
            int idx = tid + i * 256;          // 0..511
            int r   = idx >> 2;               // 0..127
            int c4  = idx & 3;                // 0..3
            float4 va = *reinterpret_cast<const float4*>(
                Ag + (size_t)(rowA0 + r) * IN_F + k0 + c4 * 4);
            As[c4 * 4 + 0][r] = va.x;
            As[c4 * 4 + 1][r] = va.y;
            As[c4 * 4 + 2][r] = va.z;
            As[c4 * 4 + 3][r] = va.w;
            float4 vb = *reinterpret_cast<const float4*>(
                Bg + (size_t)(rowB0 + r) * IN_F + k0 + c4 * 4);
            Bs[c4 * 4 + 0][r] = vb.x;
            Bs[c4 * 4 + 1][r] = vb.y;
            Bs[c4 * 4 + 2][r] = vb.z;
            Bs[c4 * 4 + 3][r] = vb.w;
        }
        __syncthreads();

#pragma unroll
        for (int k = 0; k < BK; k++) {
            float af[8], bf[8];
#pragma unroll
            for (int m = 0; m < 8; m++) af[m] = As[k][ty * 8 + m];
#pragma unroll
            for (int n = 0; n < 8; n++) bf[n] = Bs[k][tx * 8 + n];
#pragma unroll
            for (int m = 0; m < 8; m++)
#pragma unroll
                for (int n = 0; n < 8; n++) acc[m][n] += af[m] * bf[n];
        }
        __syncthreads();
    }

    // epilogue: add mixed bias, vectorized stores
    const float* bm = g_bmix + (size_t)b * OUT_F;
    float bb[8];
#pragma unroll
    for (int n = 0; n < 8; n++) bb[n] = bm[rowB0 + tx * 8 + n];

    float* Og = out + (size_t)b * A_DIM * OUT_F;
#pragma unroll
    for (int m = 0; m < 8; m++) {
        float* row = Og + (size_t)(rowA0 + ty * 8 + m) * OUT_F + rowB0 + tx * 8;
        float4 v0 = make_float4(acc[m][0] + bb[0], acc[m][1] + bb[1],
                                acc[m][2] + bb[2], acc[m][3] + bb[3]);
        float4 v1 = make_float4(acc[m][4] + bb[4], acc[m][5] + bb[5],
                                acc[m][6] + bb[6], acc[m][7] + bb[7]);
        *reinterpret_cast<float4*>(row)     = v0;
        *reinterpret_cast<float4*>(row + 4) = v1;
    }
}

// ============================================================
extern "C" void kernel_launch(void* const* d_in, const int* in_sizes, int n_in,
                              void* d_out, int out_size) {
    const float* x    = (const float*)d_in[0];   // [8,512,1024]
    const float* sp   = (const float*)d_in[1];   // [8,16]
    const float* W    = (const float*)d_in[2];   // [16,1024,1024]
    const float* bias = (const float*)d_in[3];   // [16,1024]
    float* out = (float*)d_out;                  // [8,512,1024]

    // 1) mix weights: 262144 float4 positions
    mix_weights_kernel<<<(OUT_F * IN_F / 4) / 256, 256>>>(W, sp);

    // 2) mix bias: 8192 elements
    mix_bias_kernel<<<(BATCH * OUT_F) / 256, 256>>>(bias, sp);

    // 3) batched GEMM with fused bias
    dim3 grid(OUT_F / BN, A_DIM / BM, BATCH);    // (8, 4, 8)
    gemm_kernel<<<grid, 256>>>(x, out);
}